// round 1
// baseline (speedup 1.0000x reference)
#include <cuda_runtime.h>
#include <math.h>

// Problem constants
#define BQ 2
#define NSEQ 2048
#define VV 32000
#define DD 1024
#define NLAY 4
#define NF 1025          // NSEQ/2 + 1

// ---------------------------------------------------------------------------
// Scratch (device globals; no runtime allocation allowed)
// ---------------------------------------------------------------------------
__device__ float g_x  [BQ * NSEQ * DD];          // activations [B,N,D]
__device__ float g_y  [BQ * NSEQ * DD];          // branch output / xb
__device__ float g_h  [BQ * NSEQ * 4 * DD];      // GEMM hidden (max 4096x4096)
__device__ float g_fre[BQ * NF * DD];            // rfft real  [B,NF,D]
__device__ float g_fim[BQ * NF * DD];            // rfft imag
__device__ float g_gre[BQ * NF * DD];            // freq-MLP out real
__device__ float g_gim[BQ * NF * DD];            // freq-MLP out imag
__device__ float2 g_tw[NSEQ / 2];                // twiddles exp(-2pi i k/N)

// ---------------------------------------------------------------------------
// Twiddle init (double precision -> exact enough regardless of fast-math)
// ---------------------------------------------------------------------------
__global__ void twiddle_kernel() {
    int k = threadIdx.x;   // 1024 threads
    double ang = -2.0 * 3.14159265358979323846 * (double)k / (double)NSEQ;
    g_tw[k] = make_float2((float)cos(ang), (float)sin(ang));
}

// ---------------------------------------------------------------------------
// Embedding + positional add: x[b,n,:] = embed[ids[b,n],:] + pos[n,:]
// ---------------------------------------------------------------------------
__global__ void embed_kernel(const int* __restrict__ ids,
                             const float* __restrict__ emb,
                             const float* __restrict__ pos) {
    int t = blockIdx.x * blockDim.x + threadIdx.x;   // over B*N*(D/4)
    int bn = t >> 8;                                  // D/4 = 256
    int d4 = (t & 255) << 2;
    int id = ids[bn];
    int n  = bn & (NSEQ - 1);
    float4 e = *(const float4*)(emb + (size_t)id * DD + d4);
    float4 p = *(const float4*)(pos + (size_t)n  * DD + d4);
    float4 o = make_float4(e.x + p.x, e.y + p.y, e.z + p.z, e.w + p.w);
    *(float4*)(g_x + (size_t)bn * DD + d4) = o;
}

// ---------------------------------------------------------------------------
// Radix-2 DIT FFT helpers (shared-memory, 2048 points, bit-reversed input)
// ---------------------------------------------------------------------------
__device__ __forceinline__ int bitrev11(int i) {
    return (int)(__brev((unsigned)i) >> 21);
}

template <bool INV>
__device__ __forceinline__ void fft_stages(float2* s, int tid) {
    int hbits = 0;
    for (int len = 2; len <= NSEQ; len <<= 1, hbits++) {
        int half = len >> 1;
        int step = NSEQ >> (hbits + 1);
        for (int t = tid; t < NSEQ / 2; t += 256) {
            int j   = t & (half - 1);
            int idx = ((t >> hbits) << (hbits + 1)) + j;
            float2 w = g_tw[j * step];
            if (INV) w.y = -w.y;
            float2 u = s[idx];
            float2 v = s[idx + half];
            float vwx = v.x * w.x - v.y * w.y;
            float vwy = v.x * w.y + v.y * w.x;
            s[idx]        = make_float2(u.x + vwx, u.y + vwy);
            s[idx + half] = make_float2(u.x - vwx, u.y - vwy);
        }
        __syncthreads();
    }
}

// rfft along N for one (b,d) column; writes bins 0..1024 into [B,NF,D] layout
__global__ void rfft_kernel() {
    __shared__ float2 s[NSEQ];
    int tid = threadIdx.x;
    int bd  = blockIdx.x;            // b*D + d
    int b   = bd >> 10;              // / DD
    int d   = bd & (DD - 1);
    const float* xin = g_x + (size_t)b * NSEQ * DD + d;
    for (int i = tid; i < NSEQ; i += 256)
        s[bitrev11(i)] = make_float2(xin[(size_t)i * DD], 0.0f);
    __syncthreads();
    fft_stages<false>(s, tid);
    float* re = g_fre + (size_t)b * NF * DD + d;
    float* im = g_fim + (size_t)b * NF * DD + d;
    for (int k = tid; k < NF; k += 256) {
        re[(size_t)k * DD] = s[k].x;
        im[(size_t)k * DD] = s[k].y;
    }
}

// irfft: reads [B,NF,D] spectrum, writes real signal into g_y [B,N,D]
__global__ void irfft_kernel() {
    __shared__ float2 spec[NF];
    __shared__ float2 s[NSEQ];
    int tid = threadIdx.x;
    int bd  = blockIdx.x;
    int b   = bd >> 10;
    int d   = bd & (DD - 1);
    const float* re = g_gre + (size_t)b * NF * DD + d;
    const float* im = g_gim + (size_t)b * NF * DD + d;
    for (int k = tid; k < NF; k += 256)
        spec[k] = make_float2(re[(size_t)k * DD], im[(size_t)k * DD]);
    __syncthreads();
    for (int i = tid; i < NSEQ; i += 256) {
        float2 v;
        if (i <= NSEQ / 2) v = spec[i];
        else { float2 c = spec[NSEQ - i]; v = make_float2(c.x, -c.y); }
        s[bitrev11(i)] = v;
    }
    __syncthreads();
    fft_stages<true>(s, tid);
    float* out = g_y + (size_t)b * NSEQ * DD + d;
    const float inv = 1.0f / (float)NSEQ;
    for (int n = tid; n < NSEQ; n += 256)
        out[(size_t)n * DD] = s[n].x * inv;
}

// ---------------------------------------------------------------------------
// SGEMM: C[M,N] = act(A[M,K] @ W[K,N] + bias[N]);  act: 0=none, 1=exact GELU
// 128x128 block tile, BK=8, 256 threads, 8x8 per thread
// ---------------------------------------------------------------------------
__device__ __forceinline__ float gelu_exact(float v) {
    return 0.5f * v * (1.0f + erff(v * 0.70710678118654752f));
}

__global__ void sgemm_kernel(const float* __restrict__ A,
                             const float* __restrict__ W,
                             const float* __restrict__ bias,
                             float* __restrict__ C,
                             int M, int N, int K, int act) {
    __shared__ float As[8][128];
    __shared__ float Bs[8][132];

    int tid = threadIdx.x;
    int bm  = blockIdx.y * 128;
    int bn  = blockIdx.x * 128;
    int ty  = tid >> 4;        // 0..15 -> rows ty*8..
    int tx  = tid & 15;        // 0..15 -> cols tx*8..

    int arow = tid >> 1, acol = (tid & 1) << 2;   // A tile: 128x8
    int brow = tid >> 5, bcol = (tid & 31) << 2;  // B tile: 8x128

    float acc[8][8];
#pragma unroll
    for (int i = 0; i < 8; i++)
#pragma unroll
        for (int j = 0; j < 8; j++) acc[i][j] = 0.0f;

    for (int k0 = 0; k0 < K; k0 += 8) {
        int ar = bm + arow;
        float4 av = make_float4(0.f, 0.f, 0.f, 0.f);
        if (ar < M) av = *(const float4*)(A + (size_t)ar * K + k0 + acol);
        As[acol + 0][arow] = av.x;
        As[acol + 1][arow] = av.y;
        As[acol + 2][arow] = av.z;
        As[acol + 3][arow] = av.w;

        float4 bv = *(const float4*)(W + (size_t)(k0 + brow) * N + bn + bcol);
        *(float4*)&Bs[brow][bcol] = bv;
        __syncthreads();

#pragma unroll
        for (int kk = 0; kk < 8; kk++) {
            float a[8], bb[8];
            float4 a0 = *(const float4*)&As[kk][ty * 8];
            float4 a1 = *(const float4*)&As[kk][ty * 8 + 4];
            a[0]=a0.x; a[1]=a0.y; a[2]=a0.z; a[3]=a0.w;
            a[4]=a1.x; a[5]=a1.y; a[6]=a1.z; a[7]=a1.w;
            float4 b0 = *(const float4*)&Bs[kk][tx * 8];
            float4 b1 = *(const float4*)&Bs[kk][tx * 8 + 4];
            bb[0]=b0.x; bb[1]=b0.y; bb[2]=b0.z; bb[3]=b0.w;
            bb[4]=b1.x; bb[5]=b1.y; bb[6]=b1.z; bb[7]=b1.w;
#pragma unroll
            for (int i = 0; i < 8; i++)
#pragma unroll
                for (int j = 0; j < 8; j++)
                    acc[i][j] += a[i] * bb[j];
        }
        __syncthreads();
    }

#pragma unroll
    for (int i = 0; i < 8; i++) {
        int row = bm + ty * 8 + i;
        if (row >= M) break;
        float* crow = C + (size_t)row * N + bn + tx * 8;
#pragma unroll
        for (int j = 0; j < 8; j++) {
            float v = acc[i][j] + bias[bn + tx * 8 + j];
            if (act) v = gelu_exact(v);
            crow[j] = v;
        }
    }
}

// ---------------------------------------------------------------------------
// Fused residual add + LayerNorm (in place on x): x = LN(x + y) * g + be
// One block per row (D = 1024), 256 threads, 4 elems/thread
// ---------------------------------------------------------------------------
__global__ void resid_ln_kernel(float* __restrict__ x,
                                const float* __restrict__ y,
                                const float* __restrict__ g,
                                const float* __restrict__ be) {
    __shared__ float red[256];
    int tid = threadIdx.x;
    size_t base = (size_t)blockIdx.x * DD;

    float v[4];
#pragma unroll
    for (int i = 0; i < 4; i++) {
        int d = tid + i * 256;
        v[i] = x[base + d] + y[base + d];
    }
    float s = v[0] + v[1] + v[2] + v[3];
    red[tid] = s;
    __syncthreads();
    for (int o = 128; o > 0; o >>= 1) {
        if (tid < o) red[tid] += red[tid + o];
        __syncthreads();
    }
    float mean = red[0] * (1.0f / DD);
    __syncthreads();

    float sq = 0.0f;
#pragma unroll
    for (int i = 0; i < 4; i++) { float t = v[i] - mean; sq += t * t; }
    red[tid] = sq;
    __syncthreads();
    for (int o = 128; o > 0; o >>= 1) {
        if (tid < o) red[tid] += red[tid + o];
        __syncthreads();
    }
    float var = red[0] * (1.0f / DD);
    float r = rsqrtf(var + 1e-5f);
#pragma unroll
    for (int i = 0; i < 4; i++) {
        int d = tid + i * 256;
        x[base + d] = (v[i] - mean) * r * g[d] + be[d];
    }
}

// ---------------------------------------------------------------------------
// Launcher
// ---------------------------------------------------------------------------
static float* sym(const void* s) {
    void* p = nullptr;
    cudaGetSymbolAddress(&p, s);
    return (float*)p;
}

extern "C" void kernel_launch(void* const* d_in, const int* in_sizes, int n_in,
                              void* d_out, int out_size) {
    const int*   ids  = (const int*)  d_in[0];
    const float* emb  = (const float*)d_in[1];
    const float* pos  = (const float*)d_in[2];
    const float* W1f  = (const float*)d_in[3];
    const float* b1f  = (const float*)d_in[4];
    const float* W2f  = (const float*)d_in[5];
    const float* b2f  = (const float*)d_in[6];
    const float* g1   = (const float*)d_in[7];
    const float* be1  = (const float*)d_in[8];
    const float* Wf1  = (const float*)d_in[9];
    const float* bf1  = (const float*)d_in[10];
    const float* Wf2  = (const float*)d_in[11];
    const float* bf2  = (const float*)d_in[12];
    const float* g2   = (const float*)d_in[13];
    const float* be2  = (const float*)d_in[14];
    const float* Wh   = (const float*)d_in[15];
    const float* bh   = (const float*)d_in[16];

    float* x   = sym(g_x);
    float* y   = sym(g_y);
    float* h   = sym(g_h);
    float* fre = sym(g_fre);
    float* fim = sym(g_fim);
    float* gre = sym(g_gre);
    float* gim = sym(g_gim);

    twiddle_kernel<<<1, 1024>>>();

    // x = embed[ids] + pos
    embed_kernel<<<(BQ * NSEQ * DD / 4) / 256, 256>>>(ids, emb, pos);

    const int MFREQ = BQ * NF;   // 2050
    const int MROW  = BQ * NSEQ; // 4096

    for (int l = 0; l < NLAY; l++) {
        // rfft along N
        rfft_kernel<<<BQ * DD, 256>>>();

        // freq MLP, real branch
        sgemm_kernel<<<dim3(2 * DD / 128, (MFREQ + 127) / 128), 256>>>(
            fre, W1f + (size_t)l * DD * 2 * DD, b1f + (size_t)l * 2 * DD,
            h, MFREQ, 2 * DD, DD, 1);
        sgemm_kernel<<<dim3(DD / 128, (MFREQ + 127) / 128), 256>>>(
            h, W2f + (size_t)l * 2 * DD * DD, b2f + (size_t)l * DD,
            gre, MFREQ, DD, 2 * DD, 0);

        // freq MLP, imag branch
        sgemm_kernel<<<dim3(2 * DD / 128, (MFREQ + 127) / 128), 256>>>(
            fim, W1f + (size_t)l * DD * 2 * DD, b1f + (size_t)l * 2 * DD,
            h, MFREQ, 2 * DD, DD, 1);
        sgemm_kernel<<<dim3(DD / 128, (MFREQ + 127) / 128), 256>>>(
            h, W2f + (size_t)l * 2 * DD * DD, b2f + (size_t)l * DD,
            gim, MFREQ, DD, 2 * DD, 0);

        // irfft -> y
        irfft_kernel<<<BQ * DD, 256>>>();

        // x = LN(x + y)
        resid_ln_kernel<<<MROW, 256>>>(x, y, g1 + (size_t)l * DD, be1 + (size_t)l * DD);

        // FFN
        sgemm_kernel<<<dim3(4 * DD / 128, MROW / 128), 256>>>(
            x, Wf1 + (size_t)l * DD * 4 * DD, bf1 + (size_t)l * 4 * DD,
            h, MROW, 4 * DD, DD, 1);
        sgemm_kernel<<<dim3(DD / 128, MROW / 128), 256>>>(
            h, Wf2 + (size_t)l * 4 * DD * DD, bf2 + (size_t)l * DD,
            y, MROW, DD, 4 * DD, 0);

        // x = LN(x + y)
        resid_ln_kernel<<<MROW, 256>>>(x, y, g2 + (size_t)l * DD, be2 + (size_t)l * DD);
    }

    // Head: out = x @ Wh + bh
    sgemm_kernel<<<dim3(VV / 128, MROW / 128), 256>>>(
        x, Wh, bh, (float*)d_out, MROW, VV, DD, 0);
}

// round 2
// speedup vs baseline: 1.0798x; 1.0798x over previous
#include <cuda_runtime.h>
#include <math.h>

// Problem constants
#define BQ 2
#define NSEQ 2048
#define VV 32000
#define DD 1024
#define NLAY 4
#define NF 1025          // NSEQ/2 + 1

// ---------------------------------------------------------------------------
// Scratch (device globals; no runtime allocation allowed)
// ---------------------------------------------------------------------------
__device__ float g_x [BQ * NSEQ * DD];           // activations [B,N,D]
__device__ float g_y [BQ * NSEQ * DD];           // branch output / xb
__device__ float g_h [2 * BQ * NF * 2 * DD];     // GEMM hidden (max 4100x2048 / 4096x4096)
__device__ float g_h2[BQ * NSEQ * 4 * DD];       // FFN hidden 4096x4096
__device__ float g_f [2 * BQ * NF * DD];         // rfft re (block 0) + im (block 1)
__device__ float g_go[2 * BQ * NF * DD];         // freq-MLP out re + im
__device__ float2 g_tw[NSEQ / 2];                // twiddles exp(-2pi i k/N)

// ---------------------------------------------------------------------------
// Twiddle init (double precision)
// ---------------------------------------------------------------------------
__global__ void twiddle_kernel() {
    int k = threadIdx.x;   // 1024 threads
    double ang = -2.0 * 3.14159265358979323846 * (double)k / (double)NSEQ;
    g_tw[k] = make_float2((float)cos(ang), (float)sin(ang));
}

// ---------------------------------------------------------------------------
// Embedding + positional add
// ---------------------------------------------------------------------------
__global__ void embed_kernel(const int* __restrict__ ids,
                             const float* __restrict__ emb,
                             const float* __restrict__ pos) {
    int t = blockIdx.x * blockDim.x + threadIdx.x;
    int bn = t >> 8;
    int d4 = (t & 255) << 2;
    int id = ids[bn];
    int n  = bn & (NSEQ - 1);
    float4 e = *(const float4*)(emb + (size_t)id * DD + d4);
    float4 p = *(const float4*)(pos + (size_t)n  * DD + d4);
    *(float4*)(g_x + (size_t)bn * DD + d4) =
        make_float4(e.x + p.x, e.y + p.y, e.z + p.z, e.w + p.w);
}

// ---------------------------------------------------------------------------
// Radix-2 DIT FFT (shared-memory, 2048 points)
// ---------------------------------------------------------------------------
__device__ __forceinline__ int bitrev11(int i) {
    return (int)(__brev((unsigned)i) >> 21);
}

template <bool INV>
__device__ __forceinline__ void fft_stages(float2* s, int tid) {
    int hbits = 0;
    for (int len = 2; len <= NSEQ; len <<= 1, hbits++) {
        int half = len >> 1;
        int step = NSEQ >> (hbits + 1);
        for (int t = tid; t < NSEQ / 2; t += 256) {
            int j   = t & (half - 1);
            int idx = ((t >> hbits) << (hbits + 1)) + j;
            float2 w = g_tw[j * step];
            if (INV) w.y = -w.y;
            float2 u = s[idx];
            float2 v = s[idx + half];
            float vwx = v.x * w.x - v.y * w.y;
            float vwy = v.x * w.y + v.y * w.x;
            s[idx]        = make_float2(u.x + vwx, u.y + vwy);
            s[idx + half] = make_float2(u.x - vwx, u.y - vwy);
        }
        __syncthreads();
    }
}

// rfft along N for one (b,d) column; re -> g_f[0..], im -> g_f[BQ*NF*DD..]
__global__ void rfft_kernel() {
    __shared__ float2 s[NSEQ];
    int tid = threadIdx.x;
    int bd  = blockIdx.x;
    int b   = bd >> 10;
    int d   = bd & (DD - 1);
    const float* xin = g_x + (size_t)b * NSEQ * DD + d;
    for (int i = tid; i < NSEQ; i += 256)
        s[bitrev11(i)] = make_float2(xin[(size_t)i * DD], 0.0f);
    __syncthreads();
    fft_stages<false>(s, tid);
    float* re = g_f + (size_t)b * NF * DD + d;
    float* im = g_f + (size_t)(BQ + b) * NF * DD + d;
    for (int k = tid; k < NF; k += 256) {
        re[(size_t)k * DD] = s[k].x;
        im[(size_t)k * DD] = s[k].y;
    }
}

// irfft: reads g_go (re block / im block), writes real signal into g_y
__global__ void irfft_kernel() {
    __shared__ float2 spec[NF];
    __shared__ float2 s[NSEQ];
    int tid = threadIdx.x;
    int bd  = blockIdx.x;
    int b   = bd >> 10;
    int d   = bd & (DD - 1);
    const float* re = g_go + (size_t)b * NF * DD + d;
    const float* im = g_go + (size_t)(BQ + b) * NF * DD + d;
    for (int k = tid; k < NF; k += 256)
        spec[k] = make_float2(re[(size_t)k * DD], im[(size_t)k * DD]);
    __syncthreads();
    for (int i = tid; i < NSEQ; i += 256) {
        float2 v;
        if (i <= NSEQ / 2) v = spec[i];
        else { float2 c = spec[NSEQ - i]; v = make_float2(c.x, -c.y); }
        s[bitrev11(i)] = v;
    }
    __syncthreads();
    fft_stages<true>(s, tid);
    float* out = g_y + (size_t)b * NSEQ * DD + d;
    const float inv = 1.0f / (float)NSEQ;
    for (int n = tid; n < NSEQ; n += 256)
        out[(size_t)n * DD] = s[n].x * inv;
}

// ---------------------------------------------------------------------------
// SGEMM: C = act(A[M,K] @ W[K,N] + bias); 128x128 tile, BK=16, double-buffered
// 256 threads, 8x8 microtile. N,K multiples of 16/128; M guarded.
// ---------------------------------------------------------------------------
__device__ __forceinline__ float gelu_exact(float v) {
    return 0.5f * v * (1.0f + erff(v * 0.70710678118654752f));
}

__global__ void __launch_bounds__(256, 2)
sgemm_kernel(const float* __restrict__ A,
             const float* __restrict__ W,
             const float* __restrict__ bias,
             float* __restrict__ C,
             int M, int N, int K, int act) {
    // As padded to 136 so the transposed store (stride-128 scatter) is
    // conflict-free: bank = (c*136 + row) % 32 = row + 8i, rows distinct.
    __shared__ float As[2][16][136];
    __shared__ float Bs[2][16][128];

    int tid = threadIdx.x;
    int bm  = blockIdx.y * 128;
    int bn  = blockIdx.x * 128;
    int ty  = tid >> 4;
    int tx  = tid & 15;

    // load-slot decomposition (2 float4s per thread per tile)
    int ar0 = tid >> 2,          ac0 = (tid & 3) << 2;          // slot tid
    int ar1 = (tid + 256) >> 2,  ac1 = ((tid + 256) & 3) << 2;  // slot tid+256
    int br0 = tid >> 5,          bc0 = (tid & 31) << 2;
    int br1 = (tid + 256) >> 5,  bc1 = ((tid + 256) & 31) << 2;

    float acc[8][8];
#pragma unroll
    for (int i = 0; i < 8; i++)
#pragma unroll
        for (int j = 0; j < 8; j++) acc[i][j] = 0.0f;

    float4 pa0, pa1, pb0, pb1;
    const float4 z4 = make_float4(0.f, 0.f, 0.f, 0.f);

    // prologue: load tile 0
    {
        pa0 = (bm + ar0 < M) ? *(const float4*)(A + (size_t)(bm + ar0) * K + ac0) : z4;
        pa1 = (bm + ar1 < M) ? *(const float4*)(A + (size_t)(bm + ar1) * K + ac1) : z4;
        pb0 = *(const float4*)(W + (size_t)br0 * N + bn + bc0);
        pb1 = *(const float4*)(W + (size_t)br1 * N + bn + bc1);
        As[0][ac0 + 0][ar0] = pa0.x; As[0][ac0 + 1][ar0] = pa0.y;
        As[0][ac0 + 2][ar0] = pa0.z; As[0][ac0 + 3][ar0] = pa0.w;
        As[0][ac1 + 0][ar1] = pa1.x; As[0][ac1 + 1][ar1] = pa1.y;
        As[0][ac1 + 2][ar1] = pa1.z; As[0][ac1 + 3][ar1] = pa1.w;
        *(float4*)&Bs[0][br0][bc0] = pb0;
        *(float4*)&Bs[0][br1][bc1] = pb1;
    }
    __syncthreads();

    int ntiles = K >> 4;
    int buf = 0;
    for (int t = 0; t < ntiles; t++) {
        int nk = (t + 1) << 4;
        if (t + 1 < ntiles) {
            pa0 = (bm + ar0 < M) ? *(const float4*)(A + (size_t)(bm + ar0) * K + nk + ac0) : z4;
            pa1 = (bm + ar1 < M) ? *(const float4*)(A + (size_t)(bm + ar1) * K + nk + ac1) : z4;
            pb0 = *(const float4*)(W + (size_t)(nk + br0) * N + bn + bc0);
            pb1 = *(const float4*)(W + (size_t)(nk + br1) * N + bn + bc1);
        }

#pragma unroll
        for (int kk = 0; kk < 16; kk++) {
            float a[8], bb[8];
            float4 a0 = *(const float4*)&As[buf][kk][ty * 8];
            float4 a1 = *(const float4*)&As[buf][kk][ty * 8 + 4];
            a[0]=a0.x; a[1]=a0.y; a[2]=a0.z; a[3]=a0.w;
            a[4]=a1.x; a[5]=a1.y; a[6]=a1.z; a[7]=a1.w;
            float4 b0 = *(const float4*)&Bs[buf][kk][tx * 8];
            float4 b1 = *(const float4*)&Bs[buf][kk][tx * 8 + 4];
            bb[0]=b0.x; bb[1]=b0.y; bb[2]=b0.z; bb[3]=b0.w;
            bb[4]=b1.x; bb[5]=b1.y; bb[6]=b1.z; bb[7]=b1.w;
#pragma unroll
            for (int i = 0; i < 8; i++)
#pragma unroll
                for (int j = 0; j < 8; j++)
                    acc[i][j] += a[i] * bb[j];
        }

        if (t + 1 < ntiles) {
            int nb = buf ^ 1;
            As[nb][ac0 + 0][ar0] = pa0.x; As[nb][ac0 + 1][ar0] = pa0.y;
            As[nb][ac0 + 2][ar0] = pa0.z; As[nb][ac0 + 3][ar0] = pa0.w;
            As[nb][ac1 + 0][ar1] = pa1.x; As[nb][ac1 + 1][ar1] = pa1.y;
            As[nb][ac1 + 2][ar1] = pa1.z; As[nb][ac1 + 3][ar1] = pa1.w;
            *(float4*)&Bs[nb][br0][bc0] = pb0;
            *(float4*)&Bs[nb][br1][bc1] = pb1;
            __syncthreads();
            buf = nb;
        }
    }

#pragma unroll
    for (int i = 0; i < 8; i++) {
        int row = bm + ty * 8 + i;
        if (row >= M) break;
        float* crow = C + (size_t)row * N + bn + tx * 8;
#pragma unroll
        for (int j = 0; j < 8; j++) {
            float v = acc[i][j] + bias[bn + tx * 8 + j];
            if (act) v = gelu_exact(v);
            crow[j] = v;
        }
    }
}

// ---------------------------------------------------------------------------
// Fused residual add + LayerNorm (in place on x)
// ---------------------------------------------------------------------------
__global__ void resid_ln_kernel(float* __restrict__ x,
                                const float* __restrict__ y,
                                const float* __restrict__ g,
                                const float* __restrict__ be) {
    __shared__ float red[256];
    int tid = threadIdx.x;
    size_t base = (size_t)blockIdx.x * DD;

    float v[4];
#pragma unroll
    for (int i = 0; i < 4; i++) {
        int d = tid + i * 256;
        v[i] = x[base + d] + y[base + d];
    }
    float s = v[0] + v[1] + v[2] + v[3];
    red[tid] = s;
    __syncthreads();
    for (int o = 128; o > 0; o >>= 1) {
        if (tid < o) red[tid] += red[tid + o];
        __syncthreads();
    }
    float mean = red[0] * (1.0f / DD);
    __syncthreads();

    float sq = 0.0f;
#pragma unroll
    for (int i = 0; i < 4; i++) { float t = v[i] - mean; sq += t * t; }
    red[tid] = sq;
    __syncthreads();
    for (int o = 128; o > 0; o >>= 1) {
        if (tid < o) red[tid] += red[tid + o];
        __syncthreads();
    }
    float var = red[0] * (1.0f / DD);
    float r = rsqrtf(var + 1e-5f);
#pragma unroll
    for (int i = 0; i < 4; i++) {
        int d = tid + i * 256;
        x[base + d] = (v[i] - mean) * r * g[d] + be[d];
    }
}

// ---------------------------------------------------------------------------
// Launcher
// ---------------------------------------------------------------------------
static float* sym(const void* s) {
    void* p = nullptr;
    cudaGetSymbolAddress(&p, s);
    return (float*)p;
}

extern "C" void kernel_launch(void* const* d_in, const int* in_sizes, int n_in,
                              void* d_out, int out_size) {
    const int*   ids  = (const int*)  d_in[0];
    const float* emb  = (const float*)d_in[1];
    const float* pos  = (const float*)d_in[2];
    const float* W1f  = (const float*)d_in[3];
    const float* b1f  = (const float*)d_in[4];
    const float* W2f  = (const float*)d_in[5];
    const float* b2f  = (const float*)d_in[6];
    const float* g1   = (const float*)d_in[7];
    const float* be1  = (const float*)d_in[8];
    const float* Wf1  = (const float*)d_in[9];
    const float* bf1  = (const float*)d_in[10];
    const float* Wf2  = (const float*)d_in[11];
    const float* bf2  = (const float*)d_in[12];
    const float* g2   = (const float*)d_in[13];
    const float* be2  = (const float*)d_in[14];
    const float* Wh   = (const float*)d_in[15];
    const float* bh   = (const float*)d_in[16];

    float* x  = sym(g_x);
    float* y  = sym(g_y);
    float* h  = sym(g_h);
    float* h2 = sym(g_h2);
    float* f  = sym(g_f);
    float* go = sym(g_go);

    twiddle_kernel<<<1, 1024>>>();
    embed_kernel<<<(BQ * NSEQ * DD / 4) / 256, 256>>>(ids, emb, pos);

    const int MFREQ = 2 * BQ * NF;   // 4100 (re+im batched)
    const int MROW  = BQ * NSEQ;     // 4096

    for (int l = 0; l < NLAY; l++) {
        rfft_kernel<<<BQ * DD, 256>>>();

        // freq MLP on re+im together: [4100,D] -> [4100,2D] -> [4100,D]
        sgemm_kernel<<<dim3(2 * DD / 128, (MFREQ + 127) / 128), 256>>>(
            f, W1f + (size_t)l * DD * 2 * DD, b1f + (size_t)l * 2 * DD,
            h, MFREQ, 2 * DD, DD, 1);
        sgemm_kernel<<<dim3(DD / 128, (MFREQ + 127) / 128), 256>>>(
            h, W2f + (size_t)l * 2 * DD * DD, b2f + (size_t)l * DD,
            go, MFREQ, DD, 2 * DD, 0);

        irfft_kernel<<<BQ * DD, 256>>>();

        resid_ln_kernel<<<MROW, 256>>>(x, y, g1 + (size_t)l * DD, be1 + (size_t)l * DD);

        // FFN
        sgemm_kernel<<<dim3(4 * DD / 128, MROW / 128), 256>>>(
            x, Wf1 + (size_t)l * DD * 4 * DD, bf1 + (size_t)l * 4 * DD,
            h2, MROW, 4 * DD, DD, 1);
        sgemm_kernel<<<dim3(DD / 128, MROW / 128), 256>>>(
            h2, Wf2 + (size_t)l * 4 * DD * DD, bf2 + (size_t)l * DD,
            y, MROW, DD, 4 * DD, 0);

        resid_ln_kernel<<<MROW, 256>>>(x, y, g2 + (size_t)l * DD, be2 + (size_t)l * DD);
    }

    // Head: out = x @ Wh + bh
    sgemm_kernel<<<dim3(VV / 128, MROW / 128), 256>>>(
        x, Wh, bh, (float*)d_out, MROW, VV, DD, 0);
}

// round 5
// speedup vs baseline: 2.4274x; 2.2481x over previous
#include <cuda_runtime.h>
#include <cuda_bf16.h>
#include <cstdint>
#include <math.h>

// Problem constants
#define BQ 2
#define NSEQ 2048
#define VV 32000
#define DD 1024
#define NLAY 4
#define NF 1025          // NSEQ/2 + 1

#define MPAD 4224
#define K3MAX 12288      // 3 * 4096

// MMA tiling
#define BKH 32                    // bf16 per k-tile
#define ROWH 40                   // padded row stride in halves (80 B)
#define STGH (128 * ROWH)         // halves per operand per stage
#define NSTG 3
#define SMEM_DYN (NSTG * 2 * STGH * 2)   // bytes = 61440

// ---------------------------------------------------------------------------
// Scratch (device globals)
// ---------------------------------------------------------------------------
__device__ float g_x [BQ * NSEQ * DD];
__device__ float g_y [BQ * NSEQ * DD];
__device__ float g_h [2 * BQ * NF * 2 * DD];
__device__ float g_h2[BQ * NSEQ * 4 * DD];
__device__ float g_f [2 * BQ * NF * DD];
__device__ float g_go[2 * BQ * NF * DD];
__device__ float2 g_tw[NSEQ / 2];

__device__ __nv_bfloat16 g_abf[(size_t)MPAD * K3MAX];   // A' [Mpad, 3K]
__device__ __nv_bfloat16 g_wt [(size_t)VV * 3 * DD];    // W' [N, 3K]

// ---------------------------------------------------------------------------
// PTX helpers (base sm_103-safe: cp.async / ldmatrix / mma.sync only)
// ---------------------------------------------------------------------------
__device__ __forceinline__ uint32_t cvta_smem(const void* p) {
    uint32_t a;
    asm("{ .reg .u64 t; cvta.to.shared.u64 t, %1; cvt.u32.u64 %0, t; }" : "=r"(a) : "l"(p));
    return a;
}

__device__ __forceinline__ void cp16(uint32_t dst, const void* src) {
    asm volatile("cp.async.cg.shared.global [%0], [%1], 16;" :: "r"(dst), "l"(src));
}

__device__ __forceinline__ void ldm_x4(uint32_t* r, uint32_t addr) {
    asm volatile("ldmatrix.sync.aligned.m8n8.x4.shared.b16 {%0,%1,%2,%3}, [%4];"
                 : "=r"(r[0]), "=r"(r[1]), "=r"(r[2]), "=r"(r[3]) : "r"(addr));
}

__device__ __forceinline__ void mma_bf16(float* c, const uint32_t* a, const uint32_t* b) {
    asm volatile(
        "mma.sync.aligned.m16n8k16.row.col.f32.bf16.bf16.f32 "
        "{%0,%1,%2,%3}, {%4,%5,%6,%7}, {%8,%9}, {%0,%1,%2,%3};"
        : "+f"(c[0]), "+f"(c[1]), "+f"(c[2]), "+f"(c[3])
        : "r"(a[0]), "r"(a[1]), "r"(a[2]), "r"(a[3]), "r"(b[0]), "r"(b[1]));
}

// ---------------------------------------------------------------------------
// Twiddles / embed
// ---------------------------------------------------------------------------
__global__ void twiddle_kernel() {
    int k = threadIdx.x;
    double ang = -2.0 * 3.14159265358979323846 * (double)k / (double)NSEQ;
    g_tw[k] = make_float2((float)cos(ang), (float)sin(ang));
}

__global__ void embed_kernel(const int* __restrict__ ids,
                             const float* __restrict__ emb,
                             const float* __restrict__ pos) {
    int t = blockIdx.x * blockDim.x + threadIdx.x;
    int bn = t >> 8;
    int d4 = (t & 255) << 2;
    int id = ids[bn];
    int n  = bn & (NSEQ - 1);
    float4 e = *(const float4*)(emb + (size_t)id * DD + d4);
    float4 p = *(const float4*)(pos + (size_t)n  * DD + d4);
    *(float4*)(g_x + (size_t)bn * DD + d4) =
        make_float4(e.x + p.x, e.y + p.y, e.z + p.z, e.w + p.w);
}

// ---------------------------------------------------------------------------
// FFT (unchanged)
// ---------------------------------------------------------------------------
__device__ __forceinline__ int bitrev11(int i) { return (int)(__brev((unsigned)i) >> 21); }

template <bool INV>
__device__ __forceinline__ void fft_stages(float2* s, int tid) {
    int hbits = 0;
    for (int len = 2; len <= NSEQ; len <<= 1, hbits++) {
        int half = len >> 1;
        int step = NSEQ >> (hbits + 1);
        for (int t = tid; t < NSEQ / 2; t += 256) {
            int j   = t & (half - 1);
            int idx = ((t >> hbits) << (hbits + 1)) + j;
            float2 w = g_tw[j * step];
            if (INV) w.y = -w.y;
            float2 u = s[idx];
            float2 v = s[idx + half];
            float vwx = v.x * w.x - v.y * w.y;
            float vwy = v.x * w.y + v.y * w.x;
            s[idx]        = make_float2(u.x + vwx, u.y + vwy);
            s[idx + half] = make_float2(u.x - vwx, u.y - vwy);
        }
        __syncthreads();
    }
}

__global__ void rfft_kernel() {
    __shared__ float2 s[NSEQ];
    int tid = threadIdx.x;
    int bd  = blockIdx.x;
    int b   = bd >> 10;
    int d   = bd & (DD - 1);
    const float* xin = g_x + (size_t)b * NSEQ * DD + d;
    for (int i = tid; i < NSEQ; i += 256)
        s[bitrev11(i)] = make_float2(xin[(size_t)i * DD], 0.0f);
    __syncthreads();
    fft_stages<false>(s, tid);
    float* re = g_f + (size_t)b * NF * DD + d;
    float* im = g_f + (size_t)(BQ + b) * NF * DD + d;
    for (int k = tid; k < NF; k += 256) {
        re[(size_t)k * DD] = s[k].x;
        im[(size_t)k * DD] = s[k].y;
    }
}

__global__ void irfft_kernel() {
    __shared__ float2 spec[NF];
    __shared__ float2 s[NSEQ];
    int tid = threadIdx.x;
    int bd  = blockIdx.x;
    int b   = bd >> 10;
    int d   = bd & (DD - 1);
    const float* re = g_go + (size_t)b * NF * DD + d;
    const float* im = g_go + (size_t)(BQ + b) * NF * DD + d;
    for (int k = tid; k < NF; k += 256)
        spec[k] = make_float2(re[(size_t)k * DD], im[(size_t)k * DD]);
    __syncthreads();
    for (int i = tid; i < NSEQ; i += 256) {
        float2 v;
        if (i <= NSEQ / 2) v = spec[i];
        else { float2 c = spec[NSEQ - i]; v = make_float2(c.x, -c.y); }
        s[bitrev11(i)] = v;
    }
    __syncthreads();
    fft_stages<true>(s, tid);
    float* out = g_y + (size_t)b * NSEQ * DD + d;
    const float inv = 1.0f / (float)NSEQ;
    for (int n = tid; n < NSEQ; n += 256)
        out[(size_t)n * DD] = s[n].x * inv;
}

// ---------------------------------------------------------------------------
// Conversions: fp32 -> split bf16
// A' [M,3K]: [0,K)=hi, [K,2K)=lo, [2K,3K)=hi
// W' [N,3K]: [0,K)=hi(W^T), [K,2K)=hi, [2K,3K)=lo
// ---------------------------------------------------------------------------
__global__ void convA_kernel(const float* __restrict__ A,
                             __nv_bfloat16* __restrict__ O, int M, int K) {
    int idx = blockIdx.x * blockDim.x + threadIdx.x;
    int half = K >> 1;
    if (idx >= M * half) return;
    int m = idx / half;
    int k = (idx - m * half) << 1;
    float2 a = *(const float2*)(A + (size_t)m * K + k);
    __nv_bfloat16 h0 = __float2bfloat16_rn(a.x);
    __nv_bfloat16 h1 = __float2bfloat16_rn(a.y);
    __nv_bfloat16 l0 = __float2bfloat16_rn(a.x - __bfloat162float(h0));
    __nv_bfloat16 l1 = __float2bfloat16_rn(a.y - __bfloat162float(h1));
    size_t base = (size_t)m * 3 * K + k;
    __nv_bfloat162 hh; hh.x = h0; hh.y = h1;
    __nv_bfloat162 ll; ll.x = l0; ll.y = l1;
    *(__nv_bfloat162*)(O + base)         = hh;
    *(__nv_bfloat162*)(O + base + K)     = ll;
    *(__nv_bfloat162*)(O + base + 2 * K) = hh;
}

__global__ void convW_kernel(const float* __restrict__ W,
                             __nv_bfloat16* __restrict__ O, int K, int N) {
    __shared__ float t[32][33];
    int n0 = blockIdx.x * 32, k0 = blockIdx.y * 32;
    int tx = threadIdx.x & 31, tr = threadIdx.x >> 5;
    for (int r = tr; r < 32; r += 8)
        t[r][tx] = W[(size_t)(k0 + r) * N + n0 + tx];
    __syncthreads();
    for (int r = tr; r < 32; r += 8) {
        float v = t[tx][r];                          // = W[k0+tx][n0+r]
        __nv_bfloat16 h = __float2bfloat16_rn(v);
        __nv_bfloat16 l = __float2bfloat16_rn(v - __bfloat162float(h));
        size_t b = (size_t)(n0 + r) * 3 * K + k0 + tx;
        O[b]         = h;
        O[b + K]     = h;
        O[b + 2 * K] = l;
    }
}

// ---------------------------------------------------------------------------
// HMMA GEMM: C[M,Nn] = act(A'[M,3K] @ W'^T + bias)
// 128x128 tile, BK=32, 3-stage cp.async, mma.sync m16n8k16 bf16
// ---------------------------------------------------------------------------
__device__ __forceinline__ float gelu_exact(float v) {
    return 0.5f * v * (1.0f + erff(v * 0.70710678118654752f));
}

__global__ void __launch_bounds__(256, 2)
mma_kernel(const __nv_bfloat16* __restrict__ Abf,
           const __nv_bfloat16* __restrict__ Wt,
           const float* __restrict__ bias,
           float* __restrict__ C,
           int M, int Nn, int K3, int act) {
    extern __shared__ __nv_bfloat16 sm[];
    uint32_t smBase = cvta_smem(sm);

    int tid  = threadIdx.x;
    int bn   = blockIdx.x * 128;
    int bm   = blockIdx.y * 128;
    int wid  = tid >> 5, lane = tid & 31;
    int wm   = (wid >> 2) * 64;       // warp M offset (0 or 64)
    int wn   = (wid & 3) * 32;        // warp N offset

    float c[4][4][4];
#pragma unroll
    for (int i = 0; i < 4; i++)
#pragma unroll
        for (int j = 0; j < 4; j++) {
            c[i][j][0] = 0.f; c[i][j][1] = 0.f; c[i][j][2] = 0.f; c[i][j][3] = 0.f;
        }

    // per-thread cp.async slots: 4 chunks (2 A + 2 B), 16B each
    int r0 = tid >> 2,          s0 = (tid & 3) * 8;            // chunk tid
    int r1 = (tid + 256) >> 2,  s1 = ((tid + 256) & 3) * 8;    // chunk tid+256

#define A_OFF(stg) (smBase + (uint32_t)(stg) * (2 * STGH * 2))
#define B_OFF(stg) (A_OFF(stg) + STGH * 2)

    int T = K3 >> 5;

    // prologue: stages 0,1
#pragma unroll
    for (int p = 0; p < 2; p++) {
        int k0 = p << 5;
        cp16(A_OFF(p) + (uint32_t)(r0 * ROWH + s0) * 2, Abf + (size_t)(bm + r0) * K3 + k0 + s0);
        cp16(A_OFF(p) + (uint32_t)(r1 * ROWH + s1) * 2, Abf + (size_t)(bm + r1) * K3 + k0 + s1);
        cp16(B_OFF(p) + (uint32_t)(r0 * ROWH + s0) * 2, Wt  + (size_t)(bn + r0) * K3 + k0 + s0);
        cp16(B_OFF(p) + (uint32_t)(r1 * ROWH + s1) * 2, Wt  + (size_t)(bn + r1) * K3 + k0 + s1);
        asm volatile("cp.async.commit_group;" ::: "memory");
    }

    for (int t = 0; t < T; t++) {
        asm volatile("cp.async.wait_group 1;" ::: "memory");
        __syncthreads();

        if (t + 2 < T) {
            int st = (t + 2) % NSTG;
            int k0 = (t + 2) << 5;
            cp16(A_OFF(st) + (uint32_t)(r0 * ROWH + s0) * 2, Abf + (size_t)(bm + r0) * K3 + k0 + s0);
            cp16(A_OFF(st) + (uint32_t)(r1 * ROWH + s1) * 2, Abf + (size_t)(bm + r1) * K3 + k0 + s1);
            cp16(B_OFF(st) + (uint32_t)(r0 * ROWH + s0) * 2, Wt  + (size_t)(bn + r0) * K3 + k0 + s0);
            cp16(B_OFF(st) + (uint32_t)(r1 * ROWH + s1) * 2, Wt  + (size_t)(bn + r1) * K3 + k0 + s1);
        }
        asm volatile("cp.async.commit_group;" ::: "memory");

        int st = t % NSTG;
        uint32_t aB = A_OFF(st), bB = B_OFF(st);
#pragma unroll
        for (int ks = 0; ks < 2; ks++) {
            uint32_t a[4][4];
#pragma unroll
            for (int mt = 0; mt < 4; mt++) {
                int row = wm + mt * 16 + ((lane >> 3) & 1) * 8 + (lane & 7);
                int col = ks * 16 + (lane >> 4) * 8;
                ldm_x4(a[mt], aB + (uint32_t)(row * ROWH + col) * 2);
            }
            uint32_t b[4][2];
#pragma unroll
            for (int np = 0; np < 2; np++) {
                int nrow = wn + np * 16 + (lane >> 4) * 8 + (lane & 7);
                int col  = ks * 16 + ((lane >> 3) & 1) * 8;
                uint32_t r[4];
                ldm_x4(r, bB + (uint32_t)(nrow * ROWH + col) * 2);
                b[np * 2][0]     = r[0]; b[np * 2][1]     = r[1];
                b[np * 2 + 1][0] = r[2]; b[np * 2 + 1][1] = r[3];
            }
#pragma unroll
            for (int mt = 0; mt < 4; mt++)
#pragma unroll
                for (int nt = 0; nt < 4; nt++)
                    mma_bf16(c[mt][nt], a[mt], b[nt]);
        }
    }

    // epilogue: bias + optional GELU, masked rows >= M
#pragma unroll
    for (int mt = 0; mt < 4; mt++) {
        int rowa = bm + wm + mt * 16 + (lane >> 2);
        int rowb = rowa + 8;
#pragma unroll
        for (int nt = 0; nt < 4; nt++) {
            int col = bn + wn + nt * 8 + (lane & 3) * 2;
            float b0 = bias[col], b1 = bias[col + 1];
            float v0 = c[mt][nt][0] + b0, v1 = c[mt][nt][1] + b1;
            float v2 = c[mt][nt][2] + b0, v3 = c[mt][nt][3] + b1;
            if (act) {
                v0 = gelu_exact(v0); v1 = gelu_exact(v1);
                v2 = gelu_exact(v2); v3 = gelu_exact(v3);
            }
            if (rowa < M) *(float2*)(C + (size_t)rowa * Nn + col) = make_float2(v0, v1);
            if (rowb < M) *(float2*)(C + (size_t)rowb * Nn + col) = make_float2(v2, v3);
        }
    }
#undef A_OFF
#undef B_OFF
}

// ---------------------------------------------------------------------------
// Fused residual add + LayerNorm
// ---------------------------------------------------------------------------
__global__ void resid_ln_kernel(float* __restrict__ x,
                                const float* __restrict__ y,
                                const float* __restrict__ g,
                                const float* __restrict__ be) {
    __shared__ float red[256];
    int tid = threadIdx.x;
    size_t base = (size_t)blockIdx.x * DD;

    float v[4];
#pragma unroll
    for (int i = 0; i < 4; i++) {
        int d = tid + i * 256;
        v[i] = x[base + d] + y[base + d];
    }
    float s = v[0] + v[1] + v[2] + v[3];
    red[tid] = s;
    __syncthreads();
    for (int o = 128; o > 0; o >>= 1) {
        if (tid < o) red[tid] += red[tid + o];
        __syncthreads();
    }
    float mean = red[0] * (1.0f / DD);
    __syncthreads();

    float sq = 0.0f;
#pragma unroll
    for (int i = 0; i < 4; i++) { float t = v[i] - mean; sq += t * t; }
    red[tid] = sq;
    __syncthreads();
    for (int o = 128; o > 0; o >>= 1) {
        if (tid < o) red[tid] += red[tid + o];
        __syncthreads();
    }
    float var = red[0] * (1.0f / DD);
    float r = rsqrtf(var + 1e-5f);
#pragma unroll
    for (int i = 0; i < 4; i++) {
        int d = tid + i * 256;
        x[base + d] = (v[i] - mean) * r * g[d] + be[d];
    }
}

// ---------------------------------------------------------------------------
// Launcher
// ---------------------------------------------------------------------------
static float* sym(const void* s) {
    void* p = nullptr;
    cudaGetSymbolAddress(&p, s);
    return (float*)p;
}

static void run_gemm(const float* A, const float* W, const float* bias, float* C,
                     int M, int K, int N, int act,
                     __nv_bfloat16* abf, __nv_bfloat16* wt) {
    int K3 = 3 * K;
    convA_kernel<<<(M * (K / 2) + 255) / 256, 256>>>(A, abf, M, K);
    convW_kernel<<<dim3(N / 32, K / 32), 256>>>(W, wt, K, N);
    mma_kernel<<<dim3(N / 128, (M + 127) / 128), 256, SMEM_DYN>>>(abf, wt, bias, C, M, N, K3, act);
}

extern "C" void kernel_launch(void* const* d_in, const int* in_sizes, int n_in,
                              void* d_out, int out_size) {
    const int*   ids  = (const int*)  d_in[0];
    const float* emb  = (const float*)d_in[1];
    const float* pos  = (const float*)d_in[2];
    const float* W1f  = (const float*)d_in[3];
    const float* b1f  = (const float*)d_in[4];
    const float* W2f  = (const float*)d_in[5];
    const float* b2f  = (const float*)d_in[6];
    const float* g1   = (const float*)d_in[7];
    const float* be1  = (const float*)d_in[8];
    const float* Wf1  = (const float*)d_in[9];
    const float* bf1  = (const float*)d_in[10];
    const float* Wf2  = (const float*)d_in[11];
    const float* bf2  = (const float*)d_in[12];
    const float* g2   = (const float*)d_in[13];
    const float* be2  = (const float*)d_in[14];
    const float* Wh   = (const float*)d_in[15];
    const float* bh   = (const float*)d_in[16];

    float* x  = sym(g_x);
    float* y  = sym(g_y);
    float* h  = sym(g_h);
    float* h2 = sym(g_h2);
    float* f  = sym(g_f);
    float* go = sym(g_go);
    __nv_bfloat16* abf = (__nv_bfloat16*)sym(g_abf);
    __nv_bfloat16* wt  = (__nv_bfloat16*)sym(g_wt);

    static int smem_set = 0;
    if (!smem_set) {
        cudaFuncSetAttribute(mma_kernel, cudaFuncAttributeMaxDynamicSharedMemorySize, SMEM_DYN);
        smem_set = 1;
    }

    twiddle_kernel<<<1, 1024>>>();
    embed_kernel<<<(BQ * NSEQ * DD / 4) / 256, 256>>>(ids, emb, pos);

    const int MFREQ = 2 * BQ * NF;   // 4100
    const int MROW  = BQ * NSEQ;     // 4096

    for (int l = 0; l < NLAY; l++) {
        rfft_kernel<<<BQ * DD, 256>>>();

        run_gemm(f, W1f + (size_t)l * DD * 2 * DD, b1f + (size_t)l * 2 * DD,
                 h, MFREQ, DD, 2 * DD, 1, abf, wt);
        run_gemm(h, W2f + (size_t)l * 2 * DD * DD, b2f + (size_t)l * DD,
                 go, MFREQ, 2 * DD, DD, 0, abf, wt);

        irfft_kernel<<<BQ * DD, 256>>>();
        resid_ln_kernel<<<MROW, 256>>>(x, y, g1 + (size_t)l * DD, be1 + (size_t)l * DD);

        run_gemm(x, Wf1 + (size_t)l * DD * 4 * DD, bf1 + (size_t)l * 4 * DD,
                 h2, MROW, DD, 4 * DD, 1, abf, wt);
        run_gemm(h2, Wf2 + (size_t)l * 4 * DD * DD, bf2 + (size_t)l * DD,
                 y, MROW, 4 * DD, DD, 0, abf, wt);

        resid_ln_kernel<<<MROW, 256>>>(x, y, g2 + (size_t)l * DD, be2 + (size_t)l * DD);
    }

    run_gemm(x, Wh, bh, (float*)d_out, MROW, DD, VV, 0, abf, wt);
}

// round 7
// speedup vs baseline: 2.6143x; 1.0770x over previous
#include <cuda_runtime.h>
#include <cuda_bf16.h>
#include <cstdint>
#include <math.h>

// Problem constants
#define BQ 2
#define NSEQ 2048
#define VV 32000
#define DD 1024
#define NLAY 4
#define NF 1025          // NSEQ/2 + 1

#define MPAD 4224
#define K3MAX 12288      // 3 * 4096

// MMA tiling
#define ROWH 40                   // padded row stride in halves (80 B)
#define STGH (128 * ROWH)
#define NSTG 3
#define SMEM_DYN (NSTG * 2 * STGH * 2)   // 61440 B

// ---------------------------------------------------------------------------
// Scratch (device globals)
// ---------------------------------------------------------------------------
__device__ float g_x [BQ * NSEQ * DD];
__device__ float g_y [BQ * NSEQ * DD];
__device__ float g_go[2 * BQ * NF * DD];                  // freq-MLP out re | im
__device__ float2 g_tw[NSEQ / 2];

__device__ __nv_bfloat16 g_ab1[(size_t)MPAD * 3 * DD];    // split A', K=1024 inputs
__device__ __nv_bfloat16 g_ab2[(size_t)MPAD * K3MAX];     // split A', wide (2048/4096 K)
__device__ __nv_bfloat16 g_wt [(size_t)VV * 3 * DD];      // split W' [N, 3K]

// ---------------------------------------------------------------------------
// Helpers
// ---------------------------------------------------------------------------
__device__ __forceinline__ uint32_t cvta_smem(const void* p) {
    uint32_t a;
    asm("{ .reg .u64 t; cvta.to.shared.u64 t, %1; cvt.u32.u64 %0, t; }" : "=r"(a) : "l"(p));
    return a;
}
__device__ __forceinline__ void cp16(uint32_t dst, const void* src) {
    asm volatile("cp.async.cg.shared.global [%0], [%1], 16;" :: "r"(dst), "l"(src));
}
__device__ __forceinline__ void ldm_x4(uint32_t* r, uint32_t addr) {
    asm volatile("ldmatrix.sync.aligned.m8n8.x4.shared.b16 {%0,%1,%2,%3}, [%4];"
                 : "=r"(r[0]), "=r"(r[1]), "=r"(r[2]), "=r"(r[3]) : "r"(addr));
}
__device__ __forceinline__ void mma_bf16(float* c, const uint32_t* a, const uint32_t* b) {
    asm volatile(
        "mma.sync.aligned.m16n8k16.row.col.f32.bf16.bf16.f32 "
        "{%0,%1,%2,%3}, {%4,%5,%6,%7}, {%8,%9}, {%0,%1,%2,%3};"
        : "+f"(c[0]), "+f"(c[1]), "+f"(c[2]), "+f"(c[3])
        : "r"(a[0]), "r"(a[1]), "r"(a[2]), "r"(a[3]), "r"(b[0]), "r"(b[1]));
}

// split-store a pair of adjacent values: hi,lo,hi at +0, +K, +2K (bf16x2 stores)
__device__ __forceinline__ void split_store2(__nv_bfloat16* p, int K, float a, float b) {
    __nv_bfloat16 ha = __float2bfloat16_rn(a), hb = __float2bfloat16_rn(b);
    __nv_bfloat16 la = __float2bfloat16_rn(a - __bfloat162float(ha));
    __nv_bfloat16 lb = __float2bfloat16_rn(b - __bfloat162float(hb));
    __nv_bfloat162 hh; hh.x = ha; hh.y = hb;
    __nv_bfloat162 ll; ll.x = la; ll.y = lb;
    *(__nv_bfloat162*)(p)         = hh;
    *(__nv_bfloat162*)(p + K)     = ll;
    *(__nv_bfloat162*)(p + 2 * K) = hh;
}

__device__ __forceinline__ float gelu_exact(float v) {
    return 0.5f * v * (1.0f + erff(v * 0.70710678118654752f));
}

// ---------------------------------------------------------------------------
// Twiddles / embed
// ---------------------------------------------------------------------------
__global__ void twiddle_kernel() {
    int k = threadIdx.x;
    double ang = -2.0 * 3.14159265358979323846 * (double)k / (double)NSEQ;
    g_tw[k] = make_float2((float)cos(ang), (float)sin(ang));
}

__global__ void embed_kernel(const int* __restrict__ ids,
                             const float* __restrict__ emb,
                             const float* __restrict__ pos) {
    int t = blockIdx.x * blockDim.x + threadIdx.x;
    int bn = t >> 8;
    int d4 = (t & 255) << 2;
    int id = ids[bn];
    int n  = bn & (NSEQ - 1);
    float4 e = *(const float4*)(emb + (size_t)id * DD + d4);
    float4 p = *(const float4*)(pos + (size_t)n  * DD + d4);
    *(float4*)(g_x + (size_t)bn * DD + d4) =
        make_float4(e.x + p.x, e.y + p.y, e.z + p.z, e.w + p.w);
}

// ---------------------------------------------------------------------------
// FFT core
// ---------------------------------------------------------------------------
__device__ __forceinline__ int bitrev11(int i) { return (int)(__brev((unsigned)i) >> 21); }

template <bool INV>
__device__ __forceinline__ void fft_stages(float2* s, int tid) {
    int hbits = 0;
    for (int len = 2; len <= NSEQ; len <<= 1, hbits++) {
        int half = len >> 1;
        int step = NSEQ >> (hbits + 1);
        for (int t = tid; t < NSEQ / 2; t += 256) {
            int j   = t & (half - 1);
            int idx = ((t >> hbits) << (hbits + 1)) + j;
            float2 w = g_tw[j * step];
            if (INV) w.y = -w.y;
            float2 u = s[idx];
            float2 v = s[idx + half];
            float vwx = v.x * w.x - v.y * w.y;
            float vwy = v.x * w.y + v.y * w.x;
            s[idx]        = make_float2(u.x + vwx, u.y + vwy);
            s[idx + half] = make_float2(u.x - vwx, u.y - vwy);
        }
        __syncthreads();
    }
}

// Forward: two real channels (d0, d0+1) in one complex FFT; writes split A'
// rows: re -> b*NF+k, im -> (BQ+b)*NF+k; row stride 3*DD
__global__ void rfft2_kernel(__nv_bfloat16* __restrict__ Os) {
    __shared__ float2 s[NSEQ];
    int tid = threadIdx.x;
    int b   = blockIdx.x >> 9;           // DD/2 = 512 pairs per batch
    int d0  = (blockIdx.x & 511) << 1;
    const float* x0 = g_x + (size_t)b * NSEQ * DD + d0;
    for (int i = tid; i < NSEQ; i += 256)
        s[bitrev11(i)] = *(const float2*)(x0 + (size_t)i * DD);
    __syncthreads();
    fft_stages<false>(s, tid);
    for (int k = tid; k < NF; k += 256) {
        float2 Z1 = s[k];
        float2 Z2 = s[(NSEQ - k) & (NSEQ - 1)];
        float re1 = 0.5f * (Z1.x + Z2.x), im1 = 0.5f * (Z1.y - Z2.y);
        float re2 = 0.5f * (Z1.y + Z2.y), im2 = 0.5f * (Z2.x - Z1.x);
        split_store2(Os + (size_t)(b * NF + k) * (3 * DD) + d0, DD, re1, re2);
        split_store2(Os + (size_t)((BQ + b) * NF + k) * (3 * DD) + d0, DD, im1, im2);
    }
}

// Inverse: two spectra (channels d0, d0+1) from g_go -> one complex iFFT -> g_y
__global__ void irfft2_kernel() {
    __shared__ float2 s[NSEQ];
    __shared__ float2 G1[NF];
    __shared__ float2 G2[NF];
    int tid = threadIdx.x;
    int b   = blockIdx.x >> 9;
    int d0  = (blockIdx.x & 511) << 1;
    for (int k = tid; k < NF; k += 256) {
        float2 re = *(const float2*)(g_go + (size_t)(b * NF + k) * DD + d0);
        float2 im = *(const float2*)(g_go + (size_t)((BQ + b) * NF + k) * DD + d0);
        G1[k] = make_float2(re.x, im.x);
        G2[k] = make_float2(re.y, im.y);
    }
    __syncthreads();
    for (int i = tid; i < NSEQ; i += 256) {
        float2 z;
        if (i <= NSEQ / 2) {
            float2 a = G1[i], c = G2[i];
            z = make_float2(a.x - c.y, a.y + c.x);
        } else {
            float2 a = G1[NSEQ - i], c = G2[NSEQ - i];
            z = make_float2(a.x + c.y, c.x - a.y);
        }
        s[bitrev11(i)] = z;
    }
    __syncthreads();
    fft_stages<true>(s, tid);
    float* out = g_y + (size_t)b * NSEQ * DD + d0;
    const float inv = 1.0f / (float)NSEQ;
    for (int i = tid; i < NSEQ; i += 256)
        *(float2*)(out + (size_t)i * DD) = make_float2(s[i].x * inv, s[i].y * inv);
}

// ---------------------------------------------------------------------------
// Weight conversion: W [K,N] fp32 -> W' [N,3K] split bf16 (hi, hi, lo)
// ---------------------------------------------------------------------------
__global__ void convW_kernel(const float* __restrict__ W,
                             __nv_bfloat16* __restrict__ O, int K, int N) {
    __shared__ float t[32][33];
    int n0 = blockIdx.x * 32, k0 = blockIdx.y * 32;
    int tx = threadIdx.x & 31, tr = threadIdx.x >> 5;
    for (int r = tr; r < 32; r += 8)
        t[r][tx] = W[(size_t)(k0 + r) * N + n0 + tx];
    __syncthreads();
    for (int r = tr; r < 32; r += 8) {
        float v = t[tx][r];                          // = W[k0+tx][n0+r]
        __nv_bfloat16 h = __float2bfloat16_rn(v);
        __nv_bfloat16 l = __float2bfloat16_rn(v - __bfloat162float(h));
        size_t b = (size_t)(n0 + r) * 3 * K + k0 + tx;
        O[b]         = h;
        O[b + K]     = h;
        O[b + 2 * K] = l;
    }
}

// ---------------------------------------------------------------------------
// HMMA GEMM: 128x128 tile, BK=32, 3-stage cp.async, mma.sync m16n8k16 bf16
// mode 0: fp32 out to C;  mode 1: split bf16 out to Cs (stride 3*Nn)
// grid: x = M tiles (fast), y = N tiles
// ---------------------------------------------------------------------------
__global__ void __launch_bounds__(256, 2)
mma_kernel(const __nv_bfloat16* __restrict__ Abf,
           const __nv_bfloat16* __restrict__ Wt,
           const float* __restrict__ bias,
           float* __restrict__ C,
           __nv_bfloat16* __restrict__ Cs,
           int M, int Nn, int K3, int act, int mode) {
    extern __shared__ __nv_bfloat16 sm[];
    uint32_t smBase = cvta_smem(sm);

    int tid  = threadIdx.x;
    int bm   = blockIdx.x * 128;
    int bn   = blockIdx.y * 128;
    int wid  = tid >> 5, lane = tid & 31;
    int wm   = (wid >> 2) * 64;
    int wn   = (wid & 3) * 32;

    float c[4][4][4];
#pragma unroll
    for (int i = 0; i < 4; i++)
#pragma unroll
        for (int j = 0; j < 4; j++) {
            c[i][j][0] = 0.f; c[i][j][1] = 0.f; c[i][j][2] = 0.f; c[i][j][3] = 0.f;
        }

    int r0 = tid >> 2,          s0 = (tid & 3) * 8;
    int r1 = (tid + 256) >> 2,  s1 = ((tid + 256) & 3) * 8;

#define A_OFF(stg) (smBase + (uint32_t)(stg) * (2 * STGH * 2))
#define B_OFF(stg) (A_OFF(stg) + STGH * 2)

    int T = K3 >> 5;

#pragma unroll
    for (int p = 0; p < 2; p++) {
        int k0 = p << 5;
        cp16(A_OFF(p) + (uint32_t)(r0 * ROWH + s0) * 2, Abf + (size_t)(bm + r0) * K3 + k0 + s0);
        cp16(A_OFF(p) + (uint32_t)(r1 * ROWH + s1) * 2, Abf + (size_t)(bm + r1) * K3 + k0 + s1);
        cp16(B_OFF(p) + (uint32_t)(r0 * ROWH + s0) * 2, Wt  + (size_t)(bn + r0) * K3 + k0 + s0);
        cp16(B_OFF(p) + (uint32_t)(r1 * ROWH + s1) * 2, Wt  + (size_t)(bn + r1) * K3 + k0 + s1);
        asm volatile("cp.async.commit_group;" ::: "memory");
    }

    for (int t = 0; t < T; t++) {
        asm volatile("cp.async.wait_group 1;" ::: "memory");
        __syncthreads();

        if (t + 2 < T) {
            int st = (t + 2) % NSTG;
            int k0 = (t + 2) << 5;
            cp16(A_OFF(st) + (uint32_t)(r0 * ROWH + s0) * 2, Abf + (size_t)(bm + r0) * K3 + k0 + s0);
            cp16(A_OFF(st) + (uint32_t)(r1 * ROWH + s1) * 2, Abf + (size_t)(bm + r1) * K3 + k0 + s1);
            cp16(B_OFF(st) + (uint32_t)(r0 * ROWH + s0) * 2, Wt  + (size_t)(bn + r0) * K3 + k0 + s0);
            cp16(B_OFF(st) + (uint32_t)(r1 * ROWH + s1) * 2, Wt  + (size_t)(bn + r1) * K3 + k0 + s1);
        }
        asm volatile("cp.async.commit_group;" ::: "memory");

        int st = t % NSTG;
        uint32_t aB = A_OFF(st), bB = B_OFF(st);
#pragma unroll
        for (int ks = 0; ks < 2; ks++) {
            uint32_t a[4][4];
#pragma unroll
            for (int mt = 0; mt < 4; mt++) {
                int row = wm + mt * 16 + ((lane >> 3) & 1) * 8 + (lane & 7);
                int col = ks * 16 + (lane >> 4) * 8;
                ldm_x4(a[mt], aB + (uint32_t)(row * ROWH + col) * 2);
            }
            uint32_t b[4][2];
#pragma unroll
            for (int np = 0; np < 2; np++) {
                int nrow = wn + np * 16 + (lane >> 4) * 8 + (lane & 7);
                int col  = ks * 16 + ((lane >> 3) & 1) * 8;
                uint32_t r[4];
                ldm_x4(r, bB + (uint32_t)(nrow * ROWH + col) * 2);
                b[np * 2][0]     = r[0]; b[np * 2][1]     = r[1];
                b[np * 2 + 1][0] = r[2]; b[np * 2 + 1][1] = r[3];
            }
#pragma unroll
            for (int mt = 0; mt < 4; mt++)
#pragma unroll
                for (int nt = 0; nt < 4; nt++)
                    mma_bf16(c[mt][nt], a[mt], b[nt]);
        }
    }

    // epilogue
#pragma unroll
    for (int mt = 0; mt < 4; mt++) {
        int rowa = bm + wm + mt * 16 + (lane >> 2);
        int rowb = rowa + 8;
#pragma unroll
        for (int nt = 0; nt < 4; nt++) {
            int col = bn + wn + nt * 8 + (lane & 3) * 2;
            float b0 = bias[col], b1 = bias[col + 1];
            float v0 = c[mt][nt][0] + b0, v1 = c[mt][nt][1] + b1;
            float v2 = c[mt][nt][2] + b0, v3 = c[mt][nt][3] + b1;
            if (act) {
                v0 = gelu_exact(v0); v1 = gelu_exact(v1);
                v2 = gelu_exact(v2); v3 = gelu_exact(v3);
            }
            if (mode == 0) {
                if (rowa < M) *(float2*)(C + (size_t)rowa * Nn + col) = make_float2(v0, v1);
                if (rowb < M) *(float2*)(C + (size_t)rowb * Nn + col) = make_float2(v2, v3);
            } else {
                if (rowa < M) split_store2(Cs + (size_t)rowa * 3 * Nn + col, Nn, v0, v1);
                if (rowb < M) split_store2(Cs + (size_t)rowb * 3 * Nn + col, Nn, v2, v3);
            }
        }
    }
#undef A_OFF
#undef B_OFF
}

// ---------------------------------------------------------------------------
// Fused residual add + LayerNorm; writes fp32 x and split bf16 x' (stride 3*DD)
// ---------------------------------------------------------------------------
__global__ void resid_ln_kernel(float* __restrict__ x,
                                const float* __restrict__ y,
                                const float* __restrict__ g,
                                const float* __restrict__ be,
                                __nv_bfloat16* __restrict__ xs) {
    __shared__ float red[256];
    int tid = threadIdx.x;
    size_t base = (size_t)blockIdx.x * DD;

    float v[4];
#pragma unroll
    for (int i = 0; i < 4; i++) {
        int d = tid + i * 256;
        v[i] = x[base + d] + y[base + d];
    }
    float s = v[0] + v[1] + v[2] + v[3];
    red[tid] = s;
    __syncthreads();
    for (int o = 128; o > 0; o >>= 1) {
        if (tid < o) red[tid] += red[tid + o];
        __syncthreads();
    }
    float mean = red[0] * (1.0f / DD);
    __syncthreads();

    float sq = 0.0f;
#pragma unroll
    for (int i = 0; i < 4; i++) { float t = v[i] - mean; sq += t * t; }
    red[tid] = sq;
    __syncthreads();
    for (int o = 128; o > 0; o >>= 1) {
        if (tid < o) red[tid] += red[tid + o];
        __syncthreads();
    }
    float var = red[0] * (1.0f / DD);
    float r = rsqrtf(var + 1e-5f);

    __nv_bfloat16* xrow = xs + (size_t)blockIdx.x * 3 * DD;
#pragma unroll
    for (int i = 0; i < 4; i++) {
        int d = tid + i * 256;
        float o = (v[i] - mean) * r * g[d] + be[d];
        x[base + d] = o;
        __nv_bfloat16 h = __float2bfloat16_rn(o);
        __nv_bfloat16 l = __float2bfloat16_rn(o - __bfloat162float(h));
        xrow[d]          = h;
        xrow[d + DD]     = l;
        xrow[d + 2 * DD] = h;
    }
}

// ---------------------------------------------------------------------------
// Launcher
// ---------------------------------------------------------------------------
static float* sym(const void* s) {
    void* p = nullptr;
    cudaGetSymbolAddress(&p, s);
    return (float*)p;
}

static void run_gemm(const __nv_bfloat16* Abf, const float* W, const float* bias,
                     float* C, __nv_bfloat16* Cs,
                     int M, int K, int N, int act, int mode, __nv_bfloat16* wt) {
    convW_kernel<<<dim3(N / 32, K / 32), 256>>>(W, wt, K, N);
    mma_kernel<<<dim3((M + 127) / 128, N / 128), 256, SMEM_DYN>>>(
        Abf, wt, bias, C, Cs, M, N, 3 * K, act, mode);
}

extern "C" void kernel_launch(void* const* d_in, const int* in_sizes, int n_in,
                              void* d_out, int out_size) {
    const int*   ids  = (const int*)  d_in[0];
    const float* emb  = (const float*)d_in[1];
    const float* pos  = (const float*)d_in[2];
    const float* W1f  = (const float*)d_in[3];
    const float* b1f  = (const float*)d_in[4];
    const float* W2f  = (const float*)d_in[5];
    const float* b2f  = (const float*)d_in[6];
    const float* g1   = (const float*)d_in[7];
    const float* be1  = (const float*)d_in[8];
    const float* Wf1  = (const float*)d_in[9];
    const float* bf1  = (const float*)d_in[10];
    const float* Wf2  = (const float*)d_in[11];
    const float* bf2  = (const float*)d_in[12];
    const float* g2   = (const float*)d_in[13];
    const float* be2  = (const float*)d_in[14];
    const float* Wh   = (const float*)d_in[15];
    const float* bh   = (const float*)d_in[16];

    float* x  = sym(g_x);
    float* y  = sym(g_y);
    float* go = sym(g_go);
    __nv_bfloat16* ab1 = (__nv_bfloat16*)sym(g_ab1);
    __nv_bfloat16* ab2 = (__nv_bfloat16*)sym(g_ab2);
    __nv_bfloat16* wt  = (__nv_bfloat16*)sym(g_wt);

    // Required: dynamic smem above the 48KB default. Host-side attribute set,
    // idempotent and capture-safe (not a stream operation).
    cudaFuncSetAttribute(mma_kernel, cudaFuncAttributeMaxDynamicSharedMemorySize, SMEM_DYN);

    twiddle_kernel<<<1, 1024>>>();
    embed_kernel<<<(BQ * NSEQ * DD / 4) / 256, 256>>>(ids, emb, pos);

    const int MFREQ = 2 * BQ * NF;   // 4100
    const int MROW  = BQ * NSEQ;     // 4096

    for (int l = 0; l < NLAY; l++) {
        // rfft (pack-two) -> split A' in ab1
        rfft2_kernel<<<BQ * DD / 2, 256>>>(ab1);

        // freq MLP: [4100,1024] -> [4100,2048] (split out) -> [4100,1024] fp32
        run_gemm(ab1, W1f + (size_t)l * DD * 2 * DD, b1f + (size_t)l * 2 * DD,
                 nullptr, ab2, MFREQ, DD, 2 * DD, 1, 1, wt);
        run_gemm(ab2, W2f + (size_t)l * 2 * DD * DD, b2f + (size_t)l * DD,
                 go, nullptr, MFREQ, 2 * DD, DD, 0, 0, wt);

        irfft2_kernel<<<BQ * DD / 2, 256>>>();
        resid_ln_kernel<<<MROW, 256>>>(x, y, g1 + (size_t)l * DD, be1 + (size_t)l * DD, ab1);

        // FFN: [4096,1024] -> [4096,4096] (split out) -> [4096,1024] fp32
        run_gemm(ab1, Wf1 + (size_t)l * DD * 4 * DD, bf1 + (size_t)l * 4 * DD,
                 nullptr, ab2, MROW, DD, 4 * DD, 1, 1, wt);
        run_gemm(ab2, Wf2 + (size_t)l * 4 * DD * DD, bf2 + (size_t)l * DD,
                 y, nullptr, MROW, 4 * DD, DD, 0, 0, wt);

        resid_ln_kernel<<<MROW, 256>>>(x, y, g2 + (size_t)l * DD, be2 + (size_t)l * DD, ab1);
    }

    // Head: out = x @ Wh + bh  (M-fastest raster streams 196MB W' once)
    run_gemm(ab1, Wh, bh, (float*)d_out, nullptr, MROW, DD, VV, 0, 0, wt);
}